// round 16
// baseline (speedup 1.0000x reference)
#include <cuda_runtime.h>
#include <stdint.h>

#define NB 256
#define LL 1024
#define TT 128
#define TSTRIDE 129
#define THREADS 128
#define FULL 0xffffffffu

// smem layout (bytes), all sections 16B-aligned
#define OFF_TRANST 0                       // 128*129*4 = 66048
#define OFF_BP     66048                   // 131072 -> 197120
#define OFF_TAGS   197120                  // 4096 -> 201216
#define OFF_MM     201216                  // 1024 -> 202240
#define OFF_STA    202240                  // 512 -> 202752
#define OFF_STB    202752                  // 512 -> 203264
#define OFF_WMAXS  203264                  // [2][4] u32 = 32 -> 203296
#define OFF_MASKS  203296                  // [2][4] u32 = 32 -> 203328
#define OFF_XMAXS  203328                  // [2][4] u32 = 32 -> 203360
#define OFF_DM     203360                  // 16 -> 203376
#define SMEM_BYTES 203392

__device__ int d_sched[NB];

__device__ __forceinline__ unsigned fmap(float f) {
    unsigned u = __float_as_uint(f);
    return (u & 0x80000000u) ? ~u : (u | 0x80000000u);
}
__device__ __forceinline__ float funmap(unsigned u) {
    return __uint_as_float((u & 0x80000000u) ? (u ^ 0x80000000u) : ~u);
}

// ---- pre-kernel: LPT schedule (bitonic sort, descending by length) ----
__global__ void sched_kernel(const int* __restrict__ lengths)
{
    __shared__ unsigned key[NB];
    int i = threadIdx.x;
    unsigned l = (unsigned)max(0, min(LL, lengths[i]));
    key[i] = (l << 8) | (255u - (unsigned)i);
    __syncthreads();
    for (int k = 2; k <= NB; k <<= 1) {
        for (int j = k >> 1; j > 0; j >>= 1) {
            int ixj = i ^ j;
            if (ixj > i) {
                unsigned a = key[i], b2 = key[ixj];
                bool up = ((i & k) == 0);
                bool sw = up ? (a < b2) : (a > b2);
                if (sw) { key[i] = b2; key[ixj] = a; }
            }
            __syncthreads();
        }
    }
    d_sched[i] = 255 - (int)(key[i] & 0xFFu);
}

__global__ __launch_bounds__(THREADS, 1)
void crf_decode_kernel(const float* __restrict__ x,
                       const int* __restrict__ lengths,
                       const float* __restrict__ trans,
                       float* __restrict__ out)
{
    extern __shared__ char smem[];
    float*    s_transT = (float*)(smem + OFF_TRANST);  // [j][i], stride 129
    uint8_t*  s_bp     = (uint8_t*)(smem + OFF_BP);
    int*      s_tags   = (int*)(smem + OFF_TAGS);
    float*    s_mm     = (float*)(smem + OFF_MM);
    float*    s_stA    = (float*)(smem + OFF_STA);
    float*    s_stB    = (float*)(smem + OFF_STB);
    unsigned* s_wmaxS  = (unsigned*)(smem + OFF_WMAXS); // [2][4] warp maxima of state
    unsigned* s_masks  = (unsigned*)(smem + OFF_MASKS); // [2][4] survivor masks
    unsigned* s_xmaxS  = (unsigned*)(smem + OFF_XMAXS); // [2][4] warp maxima of x row
    float*    s_DM     = (float*)(smem + OFF_DM);       // {D, minT}

    const int tid  = threadIdx.x;
    const int lane = tid & 31;
    const int w    = tid >> 5;
    const int b    = d_sched[blockIdx.x];

    int len = lengths[b];
    if (len > LL) len = LL;

    // ---- transpose trans into smem; fold per-thread min/max ----
    {
        float mx = -3.4e38f, mn = 3.4e38f;
        #pragma unroll 4
        for (int i = 0; i < TT; ++i) {
            float v = trans[i * TT + tid];
            s_transT[tid * TSTRIDE + i] = v;
            mx = fmaxf(mx, v);
            mn = fminf(mn, v);
        }
        s_mm[tid]       = mx;
        s_mm[128 + tid] = mn;
    }

    const float* xb = x + (size_t)b * (LL * TT);
    float sj = xb[tid];                        // state_0[j]

    float* stR = s_stA;
    float* stW = s_stB;
    stR[tid] = sj;
    {
        unsigned wmu = __reduce_max_sync(FULL, fmap(sj));
        if (lane == 0) s_wmaxS[4 + w] = wmu;   // slot 1 (read by t=1)
    }
    __syncthreads();

    if (tid == 0) {
        float gmx = -3.4e38f, gmn = 3.4e38f;
        for (int k = 0; k < TT; ++k) {
            gmx = fmaxf(gmx, s_mm[k]);
            gmn = fminf(gmn, s_mm[128 + k]);
        }
        float D = (gmx - gmn) * 1.001f + 0.01f;
        if (!(D >= 0.01f && D <= 1000.0f)) D = 3.0e38f;  // dense fallback
        s_DM[0] = D;
        s_DM[1] = gmn;                          // minT
    }
    __syncthreads();
    const float D    = s_DM[0];
    const float minT = s_DM[1];
    const float* rowT = s_transT + tid * TSTRIDE;

    // depth-2 x prefetch
    float xt  = (len > 1) ? xb[(size_t)1 * TT + tid] : 0.0f;  // row t (=1)
    float xn1 = (len > 2) ? xb[(size_t)2 * TT + tid] : 0.0f;  // row t+1

    // ---- pre-loop: exact ballot for step 1 + xmax stage of row 1 (slot 1) ----
    {
        unsigned gmu = max(max(s_wmaxS[4], s_wmaxS[5]), max(s_wmaxS[6], s_wmaxS[7]));
        float thr = funmap(gmu) - D;
        unsigned bal = __ballot_sync(FULL, !(sj < thr));    // NaN-safe
        if (lane == 0) s_masks[4 + w] = bal;
        unsigned xmu = __reduce_max_sync(FULL, fmap(xt));   // xmax of row 1
        if (lane == 0) s_xmaxS[4 + w] = xmu;
    }

    for (int t = 1; t < len; ++t) {
        __syncthreads();                       // THE single barrier per step
        const int rd = (t & 1) << 2;
        const int wr = rd ^ 4;

        // three parallel LDS.128 reads of the staged rings
        const uint4 mk = *(const uint4*)(s_masks + rd);
        const uint4 wm = *(const uint4*)(s_wmaxS + rd);
        const uint4 xm = *(const uint4*)(s_xmaxS + rd);

        unsigned m0 = mk.x, m1 = mk.y, m2 = mk.z, m3 = mk.w;
        if ((m0 | m1 | m2 | m3) == 0u)         // unreachable with sane D
            m0 = m1 = m2 = m3 = 0xffffffffu;

        float gmaxPrev = funmap(max(max(wm.x, wm.y), max(wm.z, wm.w)));
        float xmax_t   = funmap(max(max(xm.x, xm.y), max(xm.z, xm.w)));

        // survivor scan (ascending i, strict '>' = first-argmax)
        float best = -3.4e38f;
        int   bi   = 0;
        #pragma unroll
        for (int w2 = 0; w2 < 4; ++w2) {
            unsigned mm = (w2 == 0) ? m0 : (w2 == 1) ? m1 : (w2 == 2) ? m2 : m3;
            while (mm) {
                int l2 = __ffs(mm) - 1; mm &= mm - 1;
                int i  = (w2 << 5) + l2;
                float v = stR[i] + rowT[i];
                if (v > best) { best = v; bi = i; }
            }
        }

        s_bp[t * TT + tid] = (uint8_t)bi;
        sj = best + xt;                        // state_t[j], reference op order

        // stage xmax of row t+1 (from xn1) BEFORE shifting
        {
            unsigned xmu = __reduce_max_sync(FULL, fmap(xn1));
            if (lane == 0) s_xmaxS[wr + w] = xmu;
        }
        xt  = xn1;
        xn1 = (t + 2 < len) ? xb[(size_t)(t + 2) * TT + tid] : 0.0f;

        // publish state_t + warp max + speculative-exact ballot
        stW[tid] = sj;
        {
            unsigned wmu = __reduce_max_sync(FULL, fmap(sj));
            if (lane == 0) s_wmaxS[wr + w] = wmu;
        }
        // exact superset: gmax_t >= gmaxPrev + minT + xmax_t
        float Tspec = gmaxPrev + minT + xmax_t - D;
        unsigned bal = __ballot_sync(FULL, !(sj < Tspec));  // NaN-safe (all-pass)
        if (lane == 0) s_masks[wr + w] = bal;

        float* tmp = stR; stR = stW; stW = tmp;
    }
    __syncthreads();                           // drain last bp/state writes

    // ---- final argmax (first-max) + backward walk: thread 0 ----
    if (tid == 0) {
        float bestf = stR[0];
        int cand = 0;
        for (int i = 1; i < TT; ++i) {
            float v = stR[i];
            if (v > bestf) { bestf = v; cand = i; }
        }
        int carry = cand;
        for (int t = len - 1; t >= 1; --t) {
            s_tags[t] = carry;
            carry = (int)s_bp[t * TT + carry];
        }
        s_tags[0] = carry;
    }
    __syncthreads();

    // ---- output: float32 tags for t < len, zeros beyond ----
    float* orow = out + b * LL;
    #pragma unroll 4
    for (int k = tid; k < LL / 4; k += THREADS) {
        int base = k << 2;
        float4 v;
        v.x = (base + 0 < len) ? (float)s_tags[base + 0] : 0.0f;
        v.y = (base + 1 < len) ? (float)s_tags[base + 1] : 0.0f;
        v.z = (base + 2 < len) ? (float)s_tags[base + 2] : 0.0f;
        v.w = (base + 3 < len) ? (float)s_tags[base + 3] : 0.0f;
        ((float4*)orow)[k] = v;
    }
}

extern "C" void kernel_launch(void* const* d_in, const int* in_sizes, int n_in,
                              void* d_out, int out_size)
{
    const float* x       = nullptr;
    const int*   lengths = nullptr;
    const float* trans   = nullptr;
    for (int i = 0; i < n_in; ++i) {
        long s = in_sizes[i];
        if      (s == 33554432L || s == 134217728L) x       = (const float*)d_in[i];
        else if (s == 256L      || s == 1024L)      lengths = (const int*)d_in[i];
        else if (s == 16384L    || s == 65536L)     trans   = (const float*)d_in[i];
    }
    if (!x       && n_in > 0) x       = (const float*)d_in[0];
    if (!lengths && n_in > 1) lengths = (const int*)d_in[1];
    if (!trans   && n_in > 3) trans   = (const float*)d_in[3];

    sched_kernel<<<1, NB>>>(lengths);

    cudaFuncSetAttribute(crf_decode_kernel,
                         cudaFuncAttributeMaxDynamicSharedMemorySize, SMEM_BYTES);
    crf_decode_kernel<<<NB, THREADS, SMEM_BYTES>>>(x, lengths, trans, (float*)d_out);
}